// round 1
// baseline (speedup 1.0000x reference)
#include <cuda_runtime.h>
#include <cstdint>

// Problem constants (fixed shapes for this problem instance)
#define GN   100000      // nodes
#define GE   1600000     // edges
#define GEL  200000      // label edges
#define INC  64
#define POSC 16
#define KH   80          // INC + POSC
#define HID  64
#define OUTC 32

// ---------------- scratch (device globals; no allocation allowed) -----------
__device__ float g_dinv[GN];
__device__ float g_hw1 [GN * HID];
__device__ float g_agg1[GN * HID];
__device__ float g_hw2 [GN * OUTC];
__device__ float g_wa  [GN];
__device__ float g_wb  [GN];

// ---------------- degree / normalization ------------------------------------
__global__ void k_set_ones(float* dinv) {
    int i = blockIdx.x * blockDim.x + threadIdx.x;
    if (i < GN) dinv[i] = 1.0f;             // self-loop contributes 1 to degree
}

__global__ void k_deg_acc(const int* __restrict__ dst, float* dinv) {
    int i = blockIdx.x * blockDim.x + threadIdx.x;
    if (i < GE) atomicAdd(&dinv[dst[i]], 1.0f);
}

__global__ void k_rsqrt(float* dinv) {
    int i = blockIdx.x * blockDim.x + threadIdx.x;
    if (i < GN) dinv[i] = rsqrtf(dinv[i]);  // deg >= 1 always (self-loops)
}

// ---------------- GEMM 1: hw1 = [x | pos] @ W1  (K=80, Nout=64) -------------
// 64 rows per block, 256 threads: tx (0..15) -> 4-col quad, ty (0..15) -> 4 rows
#define KHP 81   // padded stride to dodge smem bank conflicts
__global__ __launch_bounds__(256) void k_gemm1(
    const float* __restrict__ x, const float* __restrict__ pos,
    const float* __restrict__ W1, float* __restrict__ hw1)
{
    __shared__ float sW[KH * HID];     // 20 KB
    __shared__ float sX[64 * KHP];     // 20.7 KB
    const int t = threadIdx.x;
    const int row0 = blockIdx.x * 64;

    for (int i = t; i < KH * HID; i += 256) sW[i] = W1[i];
    for (int i = t; i < 64 * INC; i += 256) {
        int r = i >> 6, c = i & 63;
        int gr = row0 + r;
        sX[r * KHP + c] = (gr < GN) ? x[gr * INC + c] : 0.0f;
    }
    for (int i = t; i < 64 * POSC; i += 256) {
        int r = i >> 4, c = i & 15;
        int gr = row0 + r;
        sX[r * KHP + INC + c] = (gr < GN) ? pos[gr * POSC + c] : 0.0f;
    }
    __syncthreads();

    const int tx = t & 15;   // col quad
    const int ty = t >> 4;   // row group (4 rows)
    float acc[4][4];
#pragma unroll
    for (int r = 0; r < 4; r++)
#pragma unroll
        for (int c = 0; c < 4; c++) acc[r][c] = 0.0f;

#pragma unroll 4
    for (int k = 0; k < KH; k++) {
        float4 w = *(const float4*)&sW[k * HID + tx * 4];
#pragma unroll
        for (int r = 0; r < 4; r++) {
            float xv = sX[(ty * 4 + r) * KHP + k];
            acc[r][0] += xv * w.x; acc[r][1] += xv * w.y;
            acc[r][2] += xv * w.z; acc[r][3] += xv * w.w;
        }
    }
#pragma unroll
    for (int r = 0; r < 4; r++) {
        int gr = row0 + ty * 4 + r;
        if (gr < GN)
            *(float4*)&hw1[gr * HID + tx * 4] =
                make_float4(acc[r][0], acc[r][1], acc[r][2], acc[r][3]);
    }
}

// ---------------- GEMM 2: hw2 = relu(agg1) @ W2  (K=64, Nout=32) ------------
// 128 rows per block, 256 threads: tx (0..7) -> 4-col quad, ty (0..31) -> 4 rows
#define HIDP 65
__global__ __launch_bounds__(256) void k_gemm2(
    const float* __restrict__ h, const float* __restrict__ W2,
    float* __restrict__ hw2)
{
    __shared__ float sW[HID * OUTC];   // 8 KB
    __shared__ float sH[128 * HIDP];   // 33.3 KB
    const int t = threadIdx.x;
    const int row0 = blockIdx.x * 128;

    for (int i = t; i < HID * OUTC; i += 256) sW[i] = W2[i];
    for (int i = t; i < 128 * HID; i += 256) {
        int r = i >> 6, c = i & 63;
        int gr = row0 + r;
        float v = (gr < GN) ? h[gr * HID + c] : 0.0f;
        sH[r * HIDP + c] = v > 0.0f ? v : 0.0f;       // fused ReLU
    }
    __syncthreads();

    const int tx = t & 7;
    const int ty = t >> 3;
    float acc[4][4];
#pragma unroll
    for (int r = 0; r < 4; r++)
#pragma unroll
        for (int c = 0; c < 4; c++) acc[r][c] = 0.0f;

#pragma unroll 4
    for (int k = 0; k < HID; k++) {
        float4 w = *(const float4*)&sW[k * OUTC + tx * 4];
#pragma unroll
        for (int r = 0; r < 4; r++) {
            float hv = sH[(ty * 4 + r) * HIDP + k];
            acc[r][0] += hv * w.x; acc[r][1] += hv * w.y;
            acc[r][2] += hv * w.z; acc[r][3] += hv * w.w;
        }
    }
#pragma unroll
    for (int r = 0; r < 4; r++) {
        int gr = row0 + ty * 4 + r;
        if (gr < GN)
            *(float4*)&hw2[gr * OUTC + tx * 4] =
                make_float4(acc[r][0], acc[r][1], acc[r][2], acc[r][3]);
    }
}

// ---------------- aggregation init: out = b[j] + vals*dinv^2 (self loop) ----
template <int LOGF>
__global__ void k_init_agg(const float* __restrict__ vals,
                           float* __restrict__ out,
                           const float* __restrict__ b,
                           const float* __restrict__ dinv, int total)
{
    int i = blockIdx.x * blockDim.x + threadIdx.x;
    if (i >= total) return;
    int node = i >> LOGF;
    int j = i & ((1 << LOGF) - 1);
    float dv = dinv[node];
    out[i] = b[j] + vals[i] * dv * dv;
}

// ---------------- edge aggregation: out[dst] += vals[src] * norm ------------
// One thread per (edge, 4-feature-quad); vectorized red.global.add.v4.f32
template <int LOGQ>   // quads per row: 16 (F=64) or 8 (F=32)
__global__ void k_agg(const float4* __restrict__ vals,
                      float4* __restrict__ out,
                      const int* __restrict__ src,
                      const int* __restrict__ dst,
                      const float* __restrict__ dinv, int total)
{
    int i = blockIdx.x * blockDim.x + threadIdx.x;
    if (i >= total) return;
    int e = i >> LOGQ;
    int q = i & ((1 << LOGQ) - 1);
    int s = __ldg(&src[e]);
    int d = __ldg(&dst[e]);
    float nm = __ldg(&dinv[s]) * __ldg(&dinv[d]);
    float4 v = __ldg(&vals[(s << LOGQ) + q]);
    float4* p = &out[(d << LOGQ) + q];
    asm volatile("red.global.add.v4.f32 [%0], {%1,%2,%3,%4};"
                 :: "l"(p), "f"(v.x * nm), "f"(v.y * nm),
                    "f"(v.z * nm), "f"(v.w * nm)
                 : "memory");
}

// ---------------- link head: wa = z.Wl[0:32], wb = z.Wl[32:64] --------------
__global__ void k_wab(const float* __restrict__ z, const float* __restrict__ Wl,
                      float* __restrict__ wa, float* __restrict__ wb)
{
    __shared__ float sWl[2 * OUTC];
    int t = threadIdx.x;
    if (t < 2 * OUTC) sWl[t] = Wl[t];
    __syncthreads();
    int i = blockIdx.x * blockDim.x + t;
    if (i >= GN) return;
    const float4* zr = (const float4*)&z[i * OUTC];
    float a = 0.0f, b = 0.0f;
#pragma unroll
    for (int q = 0; q < OUTC / 4; q++) {
        float4 v = zr[q];
        a += v.x * sWl[q*4+0] + v.y * sWl[q*4+1] + v.z * sWl[q*4+2] + v.w * sWl[q*4+3];
        b += v.x * sWl[OUTC+q*4+0] + v.y * sWl[OUTC+q*4+1]
           + v.z * sWl[OUTC+q*4+2] + v.w * sWl[OUTC+q*4+3];
    }
    wa[i] = a; wb[i] = b;
}

__global__ void k_pred(const float* __restrict__ wa, const float* __restrict__ wb,
                       const int* __restrict__ sl, const int* __restrict__ dl,
                       const float* __restrict__ bl, float* __restrict__ pred)
{
    int i = blockIdx.x * blockDim.x + threadIdx.x;
    if (i >= GEL) return;
    pred[i] = wa[__ldg(&sl[i])] + wb[__ldg(&dl[i])] + bl[0];
}

// ---------------- launch -----------------------------------------------------
extern "C" void kernel_launch(void* const* d_in, const int* in_sizes, int n_in,
                              void* d_out, int out_size)
{
    const float* x    = (const float*)d_in[0];
    const float* pos  = (const float*)d_in[1];
    const float* W1   = (const float*)d_in[2];
    const float* b1   = (const float*)d_in[3];
    const float* W2   = (const float*)d_in[4];
    const float* b2   = (const float*)d_in[5];
    const float* Wl   = (const float*)d_in[6];
    const float* bl   = (const float*)d_in[7];
    const int*   ei   = (const int*)d_in[8];   // [2, E]: src row then dst row
    const int*   eli  = (const int*)d_in[9];   // [2, EL]

    const int* src = ei;
    const int* dst = ei + GE;
    const int* sl  = eli;
    const int* dl  = eli + GEL;

    float* z    = (float*)d_out;               // [N, OUTC]
    float* pred = z + (size_t)GN * OUTC;       // [EL]

    float *dinv, *hw1, *agg1, *hw2, *wa, *wb;
    cudaGetSymbolAddress((void**)&dinv, g_dinv);
    cudaGetSymbolAddress((void**)&hw1,  g_hw1);
    cudaGetSymbolAddress((void**)&agg1, g_agg1);
    cudaGetSymbolAddress((void**)&hw2,  g_hw2);
    cudaGetSymbolAddress((void**)&wa,   g_wa);
    cudaGetSymbolAddress((void**)&wb,   g_wb);

    const int B = 256;

    // degree -> dinv
    k_set_ones<<<(GN + B - 1) / B, B>>>(dinv);
    k_deg_acc<<<(GE + B - 1) / B, B>>>(dst, dinv);
    k_rsqrt<<<(GN + B - 1) / B, B>>>(dinv);

    // layer 1
    k_gemm1<<<(GN + 63) / 64, B>>>(x, pos, W1, hw1);
    k_init_agg<6><<<(GN * HID + B - 1) / B, B>>>(hw1, agg1, b1, dinv, GN * HID);
    k_agg<4><<<(GE * 16 + B - 1) / B, B>>>((const float4*)hw1, (float4*)agg1,
                                           src, dst, dinv, GE * 16);

    // layer 2 (ReLU fused into gemm2 smem load)
    k_gemm2<<<(GN + 127) / 128, B>>>(agg1, W2, hw2);
    k_init_agg<5><<<(GN * OUTC + B - 1) / B, B>>>(hw2, z, b2, dinv, GN * OUTC);
    k_agg<3><<<(GE * 8 + B - 1) / B, B>>>((const float4*)hw2, (float4*)z,
                                          src, dst, dinv, GE * 8);

    // link-prediction head: pred = z[s].Wl_top + z[d].Wl_bot + bl
    k_wab<<<(GN + B - 1) / B, B>>>(z, Wl, wa, wb);
    k_pred<<<(GEL + B - 1) / B, B>>>(wa, wb, sl, dl, bl, pred);
}

// round 3
// speedup vs baseline: 1.0574x; 1.0574x over previous
#include <cuda_runtime.h>
#include <cstdint>

// Problem constants (fixed shapes for this problem instance)
#define GN   100000      // nodes
#define GE   1600000     // edges
#define GEL  200000      // label edges
#define INC  64
#define POSC 16
#define KH   80          // INC + POSC
#define HID  64
#define OUTC 32

// ---------------- scratch (device globals; no allocation allowed) -----------
__device__ float g_dinv[GN];
__device__ float g_hw1 [GN * HID];
__device__ float g_agg1[GN * HID];
__device__ float g_hw2 [GN * OUTC];
__device__ float g_wa  [GN];
__device__ float g_wb  [GN];

// ---------------- degree / normalization ------------------------------------
__global__ void k_set_ones(float* dinv) {
    int i = blockIdx.x * blockDim.x + threadIdx.x;
    if (i < GN) dinv[i] = 1.0f;             // self-loop contributes 1 to degree
}

__global__ void k_deg_acc(const int* __restrict__ dst, float* dinv) {
    int i = blockIdx.x * blockDim.x + threadIdx.x;
    if (i < GE) atomicAdd(&dinv[dst[i]], 1.0f);
}

__global__ void k_rsqrt(float* dinv) {
    int i = blockIdx.x * blockDim.x + threadIdx.x;
    if (i < GN) dinv[i] = rsqrtf(dinv[i]);  // deg >= 1 always (self-loops)
}

// ---------------- GEMM 1: hw1 = [x | pos] @ W1  (K=80, Nout=64) -------------
// 64 rows per block, 128 threads. Thread: 4 rows x 8 cols (32 FMA / k-step).
// Epilogue also writes agg1 = b1 + hw1 * dinv^2 (fused self-loop init).
#define KHP  81          // padded row stride for sX
#define G1_ROWS 64
__global__ __launch_bounds__(128) void k_gemm1(
    const float* __restrict__ x, const float* __restrict__ pos,
    const float* __restrict__ W1, const float* __restrict__ b1,
    const float* __restrict__ dinv,
    float* __restrict__ hw1, float* __restrict__ agg1)
{
    __shared__ float sW[KH * HID];          // 20 KB
    __shared__ float sX[G1_ROWS * KHP];     // 20.7 KB  (total 40.7 KB)
    const int t = threadIdx.x;
    const int row0 = blockIdx.x * G1_ROWS;

    for (int i = t; i < KH * HID; i += 128) sW[i] = W1[i];
    for (int i = t; i < G1_ROWS * INC; i += 128) {
        int r = i >> 6, c = i & 63;
        int gr = row0 + r;
        sX[r * KHP + c] = (gr < GN) ? x[gr * INC + c] : 0.0f;
    }
    for (int i = t; i < G1_ROWS * POSC; i += 128) {
        int r = i >> 4, c = i & 15;
        int gr = row0 + r;
        sX[r * KHP + INC + c] = (gr < GN) ? pos[gr * POSC + c] : 0.0f;
    }
    __syncthreads();

    const int tx = t & 7;    // col group: cols tx*8 .. tx*8+7
    const int ty = t >> 3;   // row group: rows ty*4 .. ty*4+3
    float acc[4][8];
#pragma unroll
    for (int r = 0; r < 4; r++)
#pragma unroll
        for (int c = 0; c < 8; c++) acc[r][c] = 0.0f;

#pragma unroll 4
    for (int k = 0; k < KH; k++) {
        float4 w0 = *(const float4*)&sW[k * HID + tx * 8];
        float4 w1 = *(const float4*)&sW[k * HID + tx * 8 + 4];
#pragma unroll
        for (int r = 0; r < 4; r++) {
            float xv = sX[(ty * 4 + r) * KHP + k];
            acc[r][0] += xv * w0.x; acc[r][1] += xv * w0.y;
            acc[r][2] += xv * w0.z; acc[r][3] += xv * w0.w;
            acc[r][4] += xv * w1.x; acc[r][5] += xv * w1.y;
            acc[r][6] += xv * w1.z; acc[r][7] += xv * w1.w;
        }
    }

    float bb[8];
#pragma unroll
    for (int c = 0; c < 8; c++) bb[c] = __ldg(&b1[tx * 8 + c]);

#pragma unroll
    for (int r = 0; r < 4; r++) {
        int gr = row0 + ty * 4 + r;
        if (gr < GN) {
            float dv = __ldg(&dinv[gr]);
            float s = dv * dv;
            *(float4*)&hw1[gr * HID + tx * 8] =
                make_float4(acc[r][0], acc[r][1], acc[r][2], acc[r][3]);
            *(float4*)&hw1[gr * HID + tx * 8 + 4] =
                make_float4(acc[r][4], acc[r][5], acc[r][6], acc[r][7]);
            *(float4*)&agg1[gr * HID + tx * 8] =
                make_float4(bb[0] + acc[r][0] * s, bb[1] + acc[r][1] * s,
                            bb[2] + acc[r][2] * s, bb[3] + acc[r][3] * s);
            *(float4*)&agg1[gr * HID + tx * 8 + 4] =
                make_float4(bb[4] + acc[r][4] * s, bb[5] + acc[r][5] * s,
                            bb[6] + acc[r][6] * s, bb[7] + acc[r][7] * s);
        }
    }
}

// ---------------- GEMM 2: hw2 = relu(agg1) @ W2  (K=64, Nout=32) ------------
// 128 rows per block, 128 threads. Thread: 4 rows x 8 cols.
// Epilogue also writes z = b2 + hw2 * dinv^2 (fused self-loop init).
#define HIDP 65
#define G2_ROWS 128
__global__ __launch_bounds__(128) void k_gemm2(
    const float* __restrict__ h, const float* __restrict__ W2,
    const float* __restrict__ b2, const float* __restrict__ dinv,
    float* __restrict__ hw2, float* __restrict__ z)
{
    __shared__ float sW[HID * OUTC];        // 8 KB
    __shared__ float sH[G2_ROWS * HIDP];    // 33.3 KB  (total 41.3 KB)
    const int t = threadIdx.x;
    const int row0 = blockIdx.x * G2_ROWS;

    for (int i = t; i < HID * OUTC; i += 128) sW[i] = W2[i];
    for (int i = t; i < G2_ROWS * HID; i += 128) {
        int r = i >> 6, c = i & 63;
        int gr = row0 + r;
        float v = (gr < GN) ? h[gr * HID + c] : 0.0f;
        sH[r * HIDP + c] = v > 0.0f ? v : 0.0f;       // fused ReLU
    }
    __syncthreads();

    const int tx = t & 3;    // col group: cols tx*8 .. tx*8+7  (4 groups x 8 = 32)
    const int ty = t >> 2;   // row group: rows ty*4 .. ty*4+3  (32 groups x 4 = 128)
    float acc[4][8];
#pragma unroll
    for (int r = 0; r < 4; r++)
#pragma unroll
        for (int c = 0; c < 8; c++) acc[r][c] = 0.0f;

#pragma unroll 4
    for (int k = 0; k < HID; k++) {
        float4 w0 = *(const float4*)&sW[k * OUTC + tx * 8];
        float4 w1 = *(const float4*)&sW[k * OUTC + tx * 8 + 4];
#pragma unroll
        for (int r = 0; r < 4; r++) {
            float hv = sH[(ty * 4 + r) * HIDP + k];
            acc[r][0] += hv * w0.x; acc[r][1] += hv * w0.y;
            acc[r][2] += hv * w0.z; acc[r][3] += hv * w0.w;
            acc[r][4] += hv * w1.x; acc[r][5] += hv * w1.y;
            acc[r][6] += hv * w1.z; acc[r][7] += hv * w1.w;
        }
    }

    float bb[8];
#pragma unroll
    for (int c = 0; c < 8; c++) bb[c] = __ldg(&b2[tx * 8 + c]);

#pragma unroll
    for (int r = 0; r < 4; r++) {
        int gr = row0 + ty * 4 + r;
        if (gr < GN) {
            float dv = __ldg(&dinv[gr]);
            float s = dv * dv;
            *(float4*)&hw2[gr * OUTC + tx * 8] =
                make_float4(acc[r][0], acc[r][1], acc[r][2], acc[r][3]);
            *(float4*)&hw2[gr * OUTC + tx * 8 + 4] =
                make_float4(acc[r][4], acc[r][5], acc[r][6], acc[r][7]);
            *(float4*)&z[gr * OUTC + tx * 8] =
                make_float4(bb[0] + acc[r][0] * s, bb[1] + acc[r][1] * s,
                            bb[2] + acc[r][2] * s, bb[3] + acc[r][3] * s);
            *(float4*)&z[gr * OUTC + tx * 8 + 4] =
                make_float4(bb[4] + acc[r][4] * s, bb[5] + acc[r][5] * s,
                            bb[6] + acc[r][6] * s, bb[7] + acc[r][7] * s);
        }
    }
}

// ---------------- edge aggregation: out[dst] += vals[src] * norm ------------
// One thread per (edge, 4-feature-quad); vectorized red.global.add.v4.f32
template <int LOGQ>   // quads per row: 16 (F=64) or 8 (F=32)
__global__ void k_agg(const float4* __restrict__ vals,
                      float4* __restrict__ out,
                      const int* __restrict__ src,
                      const int* __restrict__ dst,
                      const float* __restrict__ dinv, int total)
{
    int i = blockIdx.x * blockDim.x + threadIdx.x;
    if (i >= total) return;
    int e = i >> LOGQ;
    int q = i & ((1 << LOGQ) - 1);
    int s = __ldg(&src[e]);
    int d = __ldg(&dst[e]);
    float nm = __ldg(&dinv[s]) * __ldg(&dinv[d]);
    float4 v = __ldg(&vals[(s << LOGQ) + q]);
    float4* p = &out[(d << LOGQ) + q];
    asm volatile("red.global.add.v4.f32 [%0], {%1,%2,%3,%4};"
                 :: "l"(p), "f"(v.x * nm), "f"(v.y * nm),
                    "f"(v.z * nm), "f"(v.w * nm)
                 : "memory");
}

// ---------------- link head: wa = z.Wl[0:32], wb = z.Wl[32:64] --------------
__global__ void k_wab(const float* __restrict__ z, const float* __restrict__ Wl,
                      float* __restrict__ wa, float* __restrict__ wb)
{
    __shared__ float sWl[2 * OUTC];
    int t = threadIdx.x;
    if (t < 2 * OUTC) sWl[t] = Wl[t];
    __syncthreads();
    int i = blockIdx.x * blockDim.x + t;
    if (i >= GN) return;
    const float4* zr = (const float4*)&z[i * OUTC];
    float a = 0.0f, b = 0.0f;
#pragma unroll
    for (int q = 0; q < OUTC / 4; q++) {
        float4 v = zr[q];
        a += v.x * sWl[q*4+0] + v.y * sWl[q*4+1] + v.z * sWl[q*4+2] + v.w * sWl[q*4+3];
        b += v.x * sWl[OUTC+q*4+0] + v.y * sWl[OUTC+q*4+1]
           + v.z * sWl[OUTC+q*4+2] + v.w * sWl[OUTC+q*4+3];
    }
    wa[i] = a; wb[i] = b;
}

__global__ void k_pred(const float* __restrict__ wa, const float* __restrict__ wb,
                       const int* __restrict__ sl, const int* __restrict__ dl,
                       const float* __restrict__ bl, float* __restrict__ pred)
{
    int i = blockIdx.x * blockDim.x + threadIdx.x;
    if (i >= GEL) return;
    pred[i] = wa[__ldg(&sl[i])] + wb[__ldg(&dl[i])] + bl[0];
}

// ---------------- launch -----------------------------------------------------
extern "C" void kernel_launch(void* const* d_in, const int* in_sizes, int n_in,
                              void* d_out, int out_size)
{
    const float* x    = (const float*)d_in[0];
    const float* pos  = (const float*)d_in[1];
    const float* W1   = (const float*)d_in[2];
    const float* b1   = (const float*)d_in[3];
    const float* W2   = (const float*)d_in[4];
    const float* b2   = (const float*)d_in[5];
    const float* Wl   = (const float*)d_in[6];
    const float* bl   = (const float*)d_in[7];
    const int*   ei   = (const int*)d_in[8];   // [2, E]: src row then dst row
    const int*   eli  = (const int*)d_in[9];   // [2, EL]

    const int* src = ei;
    const int* dst = ei + GE;
    const int* sl  = eli;
    const int* dl  = eli + GEL;

    float* z    = (float*)d_out;               // [N, OUTC]
    float* pred = z + (size_t)GN * OUTC;       // [EL]

    float *dinv, *hw1, *agg1, *hw2, *wa, *wb;
    cudaGetSymbolAddress((void**)&dinv, g_dinv);
    cudaGetSymbolAddress((void**)&hw1,  g_hw1);
    cudaGetSymbolAddress((void**)&agg1, g_agg1);
    cudaGetSymbolAddress((void**)&hw2,  g_hw2);
    cudaGetSymbolAddress((void**)&wa,   g_wa);
    cudaGetSymbolAddress((void**)&wb,   g_wb);

    const int B = 256;

    // degree -> dinv
    k_set_ones<<<(GN + B - 1) / B, B>>>(dinv);
    k_deg_acc<<<(GE + B - 1) / B, B>>>(dst, dinv);
    k_rsqrt<<<(GN + B - 1) / B, B>>>(dinv);

    // layer 1 (self-loop + bias init fused into gemm epilogue)
    k_gemm1<<<(GN + G1_ROWS - 1) / G1_ROWS, 128>>>(x, pos, W1, b1, dinv, hw1, agg1);
    k_agg<4><<<(GE * 16 + B - 1) / B, B>>>((const float4*)hw1, (float4*)agg1,
                                           src, dst, dinv, GE * 16);

    // layer 2 (ReLU fused into gemm2 smem load; init fused into epilogue)
    k_gemm2<<<(GN + G2_ROWS - 1) / G2_ROWS, 128>>>(agg1, W2, b2, dinv, hw2, z);
    k_agg<3><<<(GE * 8 + B - 1) / B, B>>>((const float4*)hw2, (float4*)z,
                                          src, dst, dinv, GE * 8);

    // link-prediction head: pred = z[s].Wl_top + z[d].Wl_bot + bl
    k_wab<<<(GN + B - 1) / B, B>>>(z, Wl, wa, wb);
    k_pred<<<(GEL + B - 1) / B, B>>>(wa, wb, sl, dl, bl, pred);
}